// round 12
// baseline (speedup 1.0000x reference)
#include <cuda_runtime.h>

// ---------------- geometry ----------------
#define RAD    7
#define IMG    2048
#define DOM    2062            // IMG + 2*RAD : iterated domain
#define GUARD  8               // zero guard band around DOM (zero-pad semantics)
#define WB     2080            // buffer width in floats (GUARD+DOM+GUARD = 2078 -> 2080)
#define W4     (WB/4)          // 520
#define HB     2080            // buffer height (max row touched: 2079 by prefetch)
#define PLANE  (HB*WB)
#define NSTRIP 19              // 19 strips * 28 float4 = 532 >= 516 domain float4 cols
#define SROWS  36              // even; 5 x 58 x 3 = 870 blocks <= 148 SM x 6 = 888 (one wave)
#define NRB    58              // 57*36 = 2052; last block rows 2052..2061 = 10 (even)
#define NITER  10

// ping-pong state, planar per channel, zero-initialized at module load;
// guard bands are NEVER written -> stay zero across all graph replays
__device__ float g_bufA[3*PLANE];
__device__ float g_bufB[3*PLANE];

// ---------------- pad: img (HWC, edge-pad 7) -> bufA domain region only ----------------
__global__ void pad_kernel(const float* __restrict__ img) {
    int bc = GUARD + blockIdx.x*blockDim.x + threadIdx.x;   // domain col in buffer coords
    int br = GUARD + blockIdx.y;                            // domain row in buffer coords
    int ch = blockIdx.z;
    if (bc >= GUARD+DOM) return;
    int u = br - (GUARD+RAD);
    int w = bc - (GUARD+RAD);
    u = min(max(u,0), IMG-1);
    w = min(max(w,0), IMG-1);
    g_bufA[ch*PLANE + br*WB + bc] = img[(u*IMG + w)*3 + ch];
}

// ---------------- packed f32x2 helpers (Blackwell) ----------------
typedef unsigned long long u64;
#define NEG1P 0xBF800000BF800000ULL     // {-1.0f, -1.0f}

__device__ __forceinline__ u64 pk2(float lo, float hi){
    u64 r; asm("mov.b64 %0, {%1, %2};" : "=l"(r) : "f"(lo), "f"(hi)); return r;
}
__device__ __forceinline__ void up2(u64 v, float& lo, float& hi){
    asm("mov.b64 {%0, %1}, %2;" : "=f"(lo), "=f"(hi) : "l"(v));
}
__device__ __forceinline__ u64 fadd2(u64 a, u64 b){
    u64 r; asm("add.rn.f32x2 %0, %1, %2;" : "=l"(r) : "l"(a), "l"(b)); return r;
}
__device__ __forceinline__ u64 fmul2(u64 a, u64 b){
    u64 r; asm("mul.rn.f32x2 %0, %1, %2;" : "=l"(r) : "l"(a), "l"(b)); return r;
}
__device__ __forceinline__ u64 ffma2(u64 a, u64 b, u64 c){
    u64 r; asm("fma.rn.f32x2 %0, %1, %2, %3;" : "=l"(r) : "l"(a), "l"(b), "l"(c)); return r;
}
__device__ __forceinline__ u64 fsub2(u64 a, u64 b){     // a - b (exact: fma(b,-1,a))
    return ffma2(b, NEG1P, a);
}

struct P4 { u64 ab, cd; };               // packed float4: {x,y},{z,w}
__device__ __forceinline__ P4 p4add(P4 a, P4 b){ P4 r; r.ab=fadd2(a.ab,b.ab); r.cd=fadd2(a.cd,b.cd); return r; }
__device__ __forceinline__ P4 p4sub(P4 a, P4 b){ P4 r; r.ab=fsub2(a.ab,b.ab); r.cd=fsub2(a.cd,b.cd); return r; }
__device__ __forceinline__ P4 ldp4(const float4* p){
    float4 v = __ldg(p);
    P4 r; r.ab = pk2(v.x, v.y); r.cd = pk2(v.z, v.w); return r;
}
__device__ __forceinline__ P4 ldp4_cs(const float4* p){  // last-touch: evict-first
    float4 v = __ldcs(p);
    P4 r; r.ab = pk2(v.x, v.y); r.cd = pk2(v.z, v.w); return r;
}

// rotate-left-1 key: (abs_bits << 1) | sign  — unsigned order == |value| order,
// bijective with the float bits (recover via rotate-right-1)
__device__ __forceinline__ unsigned keyof(float d) {
    unsigned b = __float_as_uint(d);
    return __funnelshift_l(b, b, 1);
}

// 8-wide left/right window sums for this lane's 4 columns, all-shuffle exchange.
// Lane t owns chunk cols [4t, 4t+4). With w[k] = value at col 4(t-2)+k:
//   l[j] = sum w[j+1 .. j+8], r[j] = sum w[j+8 .. j+15]
__device__ __forceinline__ void awin(float ax, float ay, float az, float aw,
                                     float* l, float* r) {
    const unsigned FULL = 0xffffffffu;
    float P2 = ax + ay;
    float P3 = P2 + az;
    float S2 = az + aw;
    float S3 = ay + S2;
    float C  = P3 + aw;
    float uS1 = __shfl_up_sync  (FULL, aw, 2);
    float uS2 = __shfl_up_sync  (FULL, S2, 2);
    float uS3 = __shfl_up_sync  (FULL, S3, 2);
    float uC  = __shfl_up_sync  (FULL, C,  1);
    float dC  = __shfl_down_sync(FULL, C,  1);
    float dP1 = __shfl_down_sync(FULL, ax, 2);
    float dP2 = __shfl_down_sync(FULL, P2, 2);
    float dP3 = __shfl_down_sync(FULL, P3, 2);
    l[0] = uS3 + uC + ax;
    l[1] = uS2 + uC + P2;
    l[2] = uS1 + uC + P3;
    l[3] = uC  + C;
    r[0] = C   + dC;
    r[1] = S3  + dC + dP1;
    r[2] = S2  + dC + dP2;
    r[3] = aw  + dC + dP3;
}

// full side-window pass for one row; unconditional compute, predicated store.
// FINAL=false: store float4 into dst buffer.  FINAL=true: scatter HWC into outp.
template<bool FINAL>
__device__ __forceinline__ void do_row(P4 sT, P4 sB, P4 xc, int i,
                                       float4* __restrict__ dst4,
                                       float*  __restrict__ dstp,
                                       float*  __restrict__ outp, int ch,
                                       int c4, bool isOut, bool full4) {
    const u64 S8p  = pk2(1.0f/64.0f,  1.0f/64.0f);
    const u64 S15p = pk2(1.0f/120.0f, 1.0f/120.0f);

    // full 15-row vertical sum (packed)
    u64 sVab = fsub2(fadd2(sT.ab, sB.ab), xc.ab);
    u64 sVcd = fsub2(fadd2(sT.cd, sB.cd), xc.cd);

    float t0,t1,t2,t3, b0,b1,b2,b3, v0,v1,v2,v3;
    up2(sT.ab, t0,t1); up2(sT.cd, t2,t3);
    up2(sB.ab, b0,b1); up2(sB.cd, b2,b3);
    up2(sVab,  v0,v1); up2(sVcd,  v2,v3);

    float lT[4], rT[4], lB[4], rB[4], lV[4], rV[4];
    awin(t0,t1,t2,t3, lT, rT);
    awin(b0,b1,b2,b3, lB, rB);
    awin(v0,v1,v2,v3, lV, rV);

    float res[4];
    #pragma unroll
    for (int p = 0; p < 2; ++p) {       // pixel pairs (j0,j1) and (j2,j3)
        u64 xp  = p ? xc.cd : xc.ab;
        u64 fTp = p ? sT.cd : sT.ab;
        u64 fBp = p ? sB.cd : sB.ab;
        u64 lTp = pk2(lT[2*p], lT[2*p+1]);
        u64 rTp = pk2(rT[2*p], rT[2*p+1]);
        u64 lBp = pk2(lB[2*p], lB[2*p+1]);
        u64 rBp = pk2(rB[2*p], rB[2*p+1]);
        u64 lVp = pk2(lV[2*p], lV[2*p+1]);
        u64 rVp = pk2(rV[2*p], rV[2*p+1]);

        u64 nx  = fmul2(xp, NEG1P);                 // exact -x pair
        u64 fAp = fsub2(fadd2(lTp, rTp), fTp);      // full-15 horiz of top sums (N)
        u64 fSp = fsub2(fadd2(lBp, rBp), fBp);      // full-15 horiz of bottom sums (S)

        // channel order matches reference stack: NW NE SW SE N S W E
        u64 d0 = ffma2(lTp, S8p,  nx);
        u64 d1 = ffma2(rTp, S8p,  nx);
        u64 d2 = ffma2(lBp, S8p,  nx);
        u64 d3 = ffma2(rBp, S8p,  nx);
        u64 d4 = ffma2(fAp, S15p, nx);
        u64 d5 = ffma2(fSp, S15p, nx);
        u64 d6 = ffma2(lVp, S15p, nx);
        u64 d7 = ffma2(rVp, S15p, nx);

        float e0,f0_, e1,f1_, e2,f2_, e3,f3_, e4,f4_, e5,f5_, e6,f6_, e7,f7_;
        up2(d0, e0,f0_); up2(d1, e1,f1_); up2(d2, e2,f2_); up2(d3, e3,f3_);
        up2(d4, e4,f4_); up2(d5, e5,f5_); up2(d6, e6,f6_); up2(d7, e7,f7_);
        float xlo, xhi; up2(xp, xlo, xhi);

        {   // element 2p : min-|d| via rotated-bits unsigned keys, depth-3 IMNMX tree
            unsigned m = min(min(min(keyof(e0),keyof(e1)), min(keyof(e2),keyof(e3))),
                             min(min(keyof(e4),keyof(e5)), min(keyof(e6),keyof(e7))));
            res[2*p] = xlo + __uint_as_float(__funnelshift_r(m, m, 1));
        }
        {   // element 2p+1
            unsigned m = min(min(min(keyof(f0_),keyof(f1_)), min(keyof(f2_),keyof(f3_))),
                             min(min(keyof(f4_),keyof(f5_)), min(keyof(f6_),keyof(f7_))));
            res[2*p+1] = xhi + __uint_as_float(__funnelshift_r(m, m, 1));
        }
    }

    if (FINAL) {
        // write crop region directly to d_out (HWC); no buffer write needed
        int y = i - RAD;
        if (isOut && (unsigned)y < (unsigned)IMG) {
            #pragma unroll
            for (int j = 0; j < 4; ++j) {
                int x = 4*c4 + j - (GUARD+RAD);
                if ((unsigned)x < (unsigned)IMG)
                    outp[((size_t)y*IMG + x)*3 + ch] = res[j];
            }
        }
    } else {
        if (isOut & full4) {
            dst4[(i+8)*W4 + c4] = make_float4(res[0], res[1], res[2], res[3]);
        } else if (isOut) {
            // c4 == 517: only buffer cols 2068, 2069 are inside the domain
            dstp[(i+8)*WB + 4*c4 + 0] = res[0];
            dstp[(i+8)*WB + 4*c4 + 1] = res[1];
        }
    }
}

// ---------------- one full side-window iteration, 2 rows per loop ----------------
template<bool FINAL>
__global__ __launch_bounds__(128,6) void iter_kernel_t(int sel, float* __restrict__ outp) {
    const int t = threadIdx.x & 31;
    const int w = threadIdx.x >> 5;
    const int strip = blockIdx.x*4 + w;
    if (strip >= NSTRIP) return;      // warps fully independent, no block sync anywhere
    const int ch = blockIdx.z;
    const float* __restrict__ srcp = (sel ? g_bufB : g_bufA) + ch*PLANE;
    float*       __restrict__ dstp = (sel ? g_bufA : g_bufB) + ch*PLANE;
    const float4* __restrict__ src4 = reinterpret_cast<const float4*>(srcp);
    float4*       __restrict__ dst4 = reinterpret_cast<float4*>(dstp);

    const int c4 = strip*28 + t;      // buffer float4 column (max 535; see halo note)
    const int r0 = blockIdx.y*SROWS;
    const int rend = min(r0 + SROWS, DOM);   // rend - r0 always even (36 or 10)

    // warm-up: sT = buffer rows r0+1..r0+8, sB = rows r0+8..r0+15, xc = row r0+8
    P4 sT; sT.ab = 0; sT.cd = 0;
    P4 sB; sB.ab = 0; sB.cd = 0;
    P4 xc; xc.ab = 0; xc.cd = 0;
    #pragma unroll
    for (int k = 1; k <= 15; ++k) {
        P4 v = ldp4(&src4[(r0+k)*W4 + c4]);
        if (k <= 8) sT = p4add(sT, v);
        if (k >= 8) sB = p4add(sB, v);
        if (k == 8) xc = v;
    }

    const bool isOut = (t >= 2) && (t < 30) && (c4 <= 517);
    const bool full4 = (c4 <= 516);

    // prefetch first pair's first-touch rows (i+16, i+17)
    P4 pC = ldp4(&src4[(r0+16)*W4 + c4]);
    P4 pF = ldp4(&src4[(r0+17)*W4 + c4]);

    for (int i = r0; i < rend; i += 2) {
        // re-read rows (L1-resident) + last-touch rows (evict-first)
        P4 rA = ldp4   (&src4[(i+9)*W4  + c4]);   // aT for row i; center of row i+1
        P4 rB = ldp4_cs(&src4[(i+1)*W4  + c4]);   // bT for row i (last touch)
        P4 rD = ldp4   (&src4[(i+10)*W4 + c4]);   // aT for row i+1; next center
        P4 rE = ldp4_cs(&src4[(i+2)*W4  + c4]);   // bT for row i+1 (last touch)
        P4 rC = pC;                               // aB for row i   (prefetched)
        P4 rF = pF;                               // aB for row i+1 (prefetched)
        // prefetch next pair's first-touch rows (rows <= 2079 < HB, always in-bounds)
        pC = ldp4(&src4[(i+18)*W4 + c4]);
        pF = ldp4(&src4[(i+19)*W4 + c4]);

        do_row<FINAL>(sT, sB, xc, i, dst4, dstp, outp, ch, c4, isOut, full4);

        P4 sT1 = p4sub(p4add(sT, rA), rB);
        P4 sB1 = p4sub(p4add(sB, rC), xc);

        do_row<FINAL>(sT1, sB1, rA, i+1, dst4, dstp, outp, ch, c4, isOut, full4);

        sT = p4sub(p4add(sT1, rD), rE);
        sB = p4sub(p4add(sB1, rF), rA);
        xc = rD;
    }
}

extern "C" void kernel_launch(void* const* d_in, const int* in_sizes, int n_in,
                              void* d_out, int out_size) {
    (void)in_sizes; (void)n_in; (void)out_size;
    const float* img = (const float*)d_in[0];   // d_in[1], d_in[2] are fixed constant kernels
    float* out = (float*)d_out;

    pad_kernel<<<dim3((DOM + 255)/256, DOM, 3), 256>>>(img);

    // iterations 0..8 ping-pong between buffers (it0: A->B, it8: A->B)
    for (int it = 0; it < NITER-1; ++it)
        iter_kernel_t<false><<<dim3(5, NRB, 3), 128>>>(it & 1, nullptr);

    // final iteration reads bufB, writes the cropped result directly to d_out (HWC)
    iter_kernel_t<true><<<dim3(5, NRB, 3), 128>>>(1, out);
}

// round 13
// speedup vs baseline: 1.0065x; 1.0065x over previous
#include <cuda_runtime.h>

// ---------------- geometry ----------------
#define RAD    7
#define IMG    2048
#define DOM    2062            // IMG + 2*RAD : iterated domain
#define GUARD  8               // zero guard band around DOM (zero-pad semantics)
#define WB     2176            // buffer width in floats
#define W4     (WB/4)
#define HB     2080            // buffer height
#define PLANE  (HB*WB)
#define NSTRIP 19              // 19 strips * 28 float4 = 532 >= 516 domain float4 cols
#define SROWS  36              // even; 5 x 58 x 3 = 870 blocks <= 148 SM x 6 = 888 (one wave)
#define NRB    58              // 57*36 = 2052; last block rows 2052..2061 = 10 (even)
#define NITER  10

// ping-pong state, planar per channel, zero-initialized at module load;
// guard bands are NEVER written -> stay zero across all graph replays
__device__ float g_bufA[3*PLANE];
__device__ float g_bufB[3*PLANE];

// ---------------- pad: img (HWC, edge-pad 7) -> bufA domain region only ----------------
__global__ void pad_kernel(const float* __restrict__ img) {
    int bc = GUARD + blockIdx.x*blockDim.x + threadIdx.x;   // domain col in buffer coords
    int br = GUARD + blockIdx.y;                            // domain row in buffer coords
    int ch = blockIdx.z;
    if (bc >= GUARD+DOM) return;
    int u = br - (GUARD+RAD);
    int w = bc - (GUARD+RAD);
    u = min(max(u,0), IMG-1);
    w = min(max(w,0), IMG-1);
    g_bufA[ch*PLANE + br*WB + bc] = img[(u*IMG + w)*3 + ch];
}

// ---------------- packed f32x2 helpers (Blackwell) ----------------
typedef unsigned long long u64;
#define NEG1P 0xBF800000BF800000ULL     // {-1.0f, -1.0f}

__device__ __forceinline__ u64 pk2(float lo, float hi){
    u64 r; asm("mov.b64 %0, {%1, %2};" : "=l"(r) : "f"(lo), "f"(hi)); return r;
}
__device__ __forceinline__ void up2(u64 v, float& lo, float& hi){
    asm("mov.b64 {%0, %1}, %2;" : "=f"(lo), "=f"(hi) : "l"(v));
}
__device__ __forceinline__ u64 fadd2(u64 a, u64 b){
    u64 r; asm("add.rn.f32x2 %0, %1, %2;" : "=l"(r) : "l"(a), "l"(b)); return r;
}
__device__ __forceinline__ u64 fmul2(u64 a, u64 b){
    u64 r; asm("mul.rn.f32x2 %0, %1, %2;" : "=l"(r) : "l"(a), "l"(b)); return r;
}
__device__ __forceinline__ u64 ffma2(u64 a, u64 b, u64 c){
    u64 r; asm("fma.rn.f32x2 %0, %1, %2, %3;" : "=l"(r) : "l"(a), "l"(b), "l"(c)); return r;
}
__device__ __forceinline__ u64 fsub2(u64 a, u64 b){     // a - b (exact: fma(b,-1,a))
    return ffma2(b, NEG1P, a);
}

struct P4 { u64 ab, cd; };               // packed float4: {x,y},{z,w}
__device__ __forceinline__ P4 p4add(P4 a, P4 b){ P4 r; r.ab=fadd2(a.ab,b.ab); r.cd=fadd2(a.cd,b.cd); return r; }
__device__ __forceinline__ P4 p4sub(P4 a, P4 b){ P4 r; r.ab=fsub2(a.ab,b.ab); r.cd=fsub2(a.cd,b.cd); return r; }
__device__ __forceinline__ P4 ldp4(const float4* p){
    float4 v = __ldg(p);
    P4 r; r.ab = pk2(v.x, v.y); r.cd = pk2(v.z, v.w); return r;
}

// rotate-left-1 key: (abs_bits << 1) | sign  — unsigned order == |value| order,
// bijective with the float bits (recover via rotate-right-1)
__device__ __forceinline__ unsigned keyof(float d) {
    unsigned b = __float_as_uint(d);
    return __funnelshift_l(b, b, 1);
}

// 8-wide left/right window sums for this lane's 4 columns, all-shuffle exchange.
// Lane t owns chunk cols [4t, 4t+4). With w[k] = value at col 4(t-2)+k:
//   l[j] = sum w[j+1 .. j+8], r[j] = sum w[j+8 .. j+15]
__device__ __forceinline__ void awin(float ax, float ay, float az, float aw,
                                     float* l, float* r) {
    const unsigned FULL = 0xffffffffu;
    float P2 = ax + ay;
    float P3 = P2 + az;
    float S2 = az + aw;
    float S3 = ay + S2;
    float C  = P3 + aw;
    float uS1 = __shfl_up_sync  (FULL, aw, 2);
    float uS2 = __shfl_up_sync  (FULL, S2, 2);
    float uS3 = __shfl_up_sync  (FULL, S3, 2);
    float uC  = __shfl_up_sync  (FULL, C,  1);
    float dC  = __shfl_down_sync(FULL, C,  1);
    float dP1 = __shfl_down_sync(FULL, ax, 2);
    float dP2 = __shfl_down_sync(FULL, P2, 2);
    float dP3 = __shfl_down_sync(FULL, P3, 2);
    l[0] = uS3 + uC + ax;
    l[1] = uS2 + uC + P2;
    l[2] = uS1 + uC + P3;
    l[3] = uC  + C;
    r[0] = C   + dC;
    r[1] = S3  + dC + dP1;
    r[2] = S2  + dC + dP2;
    r[3] = aw  + dC + dP3;
}

// full side-window pass for one row; unconditional compute, predicated store.
// FINAL=false: store float4 into dst buffer.  FINAL=true: scatter HWC into outp.
template<bool FINAL>
__device__ __forceinline__ void do_row(P4 sT, P4 sB, P4 xc, int i,
                                       float4* __restrict__ dst4,
                                       float*  __restrict__ dstp,
                                       float*  __restrict__ outp, int ch,
                                       int c4, bool isOut, bool full4) {
    const u64 S8p  = pk2(1.0f/64.0f,  1.0f/64.0f);
    const u64 S15p = pk2(1.0f/120.0f, 1.0f/120.0f);

    // full 15-row vertical sum (packed)
    u64 sVab = fsub2(fadd2(sT.ab, sB.ab), xc.ab);
    u64 sVcd = fsub2(fadd2(sT.cd, sB.cd), xc.cd);

    float t0,t1,t2,t3, b0,b1,b2,b3, v0,v1,v2,v3;
    up2(sT.ab, t0,t1); up2(sT.cd, t2,t3);
    up2(sB.ab, b0,b1); up2(sB.cd, b2,b3);
    up2(sVab,  v0,v1); up2(sVcd,  v2,v3);

    float lT[4], rT[4], lB[4], rB[4], lV[4], rV[4];
    awin(t0,t1,t2,t3, lT, rT);
    awin(b0,b1,b2,b3, lB, rB);
    awin(v0,v1,v2,v3, lV, rV);

    float res[4];
    #pragma unroll
    for (int p = 0; p < 2; ++p) {       // pixel pairs (j0,j1) and (j2,j3)
        u64 xp  = p ? xc.cd : xc.ab;
        u64 fTp = p ? sT.cd : sT.ab;
        u64 fBp = p ? sB.cd : sB.ab;
        u64 lTp = pk2(lT[2*p], lT[2*p+1]);
        u64 rTp = pk2(rT[2*p], rT[2*p+1]);
        u64 lBp = pk2(lB[2*p], lB[2*p+1]);
        u64 rBp = pk2(rB[2*p], rB[2*p+1]);
        u64 lVp = pk2(lV[2*p], lV[2*p+1]);
        u64 rVp = pk2(rV[2*p], rV[2*p+1]);

        u64 nx  = fmul2(xp, NEG1P);                 // exact -x pair
        u64 fAp = fsub2(fadd2(lTp, rTp), fTp);      // full-15 horiz of top sums (N)
        u64 fSp = fsub2(fadd2(lBp, rBp), fBp);      // full-15 horiz of bottom sums (S)

        // channel order matches reference stack: NW NE SW SE N S W E
        u64 d0 = ffma2(lTp, S8p,  nx);
        u64 d1 = ffma2(rTp, S8p,  nx);
        u64 d2 = ffma2(lBp, S8p,  nx);
        u64 d3 = ffma2(rBp, S8p,  nx);
        u64 d4 = ffma2(fAp, S15p, nx);
        u64 d5 = ffma2(fSp, S15p, nx);
        u64 d6 = ffma2(lVp, S15p, nx);
        u64 d7 = ffma2(rVp, S15p, nx);

        float e0,f0_, e1,f1_, e2,f2_, e3,f3_, e4,f4_, e5,f5_, e6,f6_, e7,f7_;
        up2(d0, e0,f0_); up2(d1, e1,f1_); up2(d2, e2,f2_); up2(d3, e3,f3_);
        up2(d4, e4,f4_); up2(d5, e5,f5_); up2(d6, e6,f6_); up2(d7, e7,f7_);
        float xlo, xhi; up2(xp, xlo, xhi);

        {   // element 2p : min-|d| via rotated-bits unsigned keys, depth-3 IMNMX tree
            unsigned m = min(min(min(keyof(e0),keyof(e1)), min(keyof(e2),keyof(e3))),
                             min(min(keyof(e4),keyof(e5)), min(keyof(e6),keyof(e7))));
            res[2*p] = xlo + __uint_as_float(__funnelshift_r(m, m, 1));
        }
        {   // element 2p+1
            unsigned m = min(min(min(keyof(f0_),keyof(f1_)), min(keyof(f2_),keyof(f3_))),
                             min(min(keyof(f4_),keyof(f5_)), min(keyof(f6_),keyof(f7_))));
            res[2*p+1] = xhi + __uint_as_float(__funnelshift_r(m, m, 1));
        }
    }

    if (FINAL) {
        // write crop region directly to d_out (HWC); no buffer write needed
        int y = i - RAD;
        if (isOut && (unsigned)y < (unsigned)IMG) {
            #pragma unroll
            for (int j = 0; j < 4; ++j) {
                int x = 4*c4 + j - (GUARD+RAD);
                if ((unsigned)x < (unsigned)IMG)
                    outp[((size_t)y*IMG + x)*3 + ch] = res[j];
            }
        }
    } else {
        if (isOut & full4) {
            dst4[(i+8)*W4 + c4] = make_float4(res[0], res[1], res[2], res[3]);
        } else if (isOut) {
            // c4 == 517: only buffer cols 2068, 2069 are inside the domain
            dstp[(i+8)*WB + 4*c4 + 0] = res[0];
            dstp[(i+8)*WB + 4*c4 + 1] = res[1];
        }
    }
}

// ---------------- one full side-window iteration, 2 rows per loop ----------------
template<bool FINAL>
__global__ __launch_bounds__(128,6) void iter_kernel_t(int sel, float* __restrict__ outp) {
    const int t = threadIdx.x & 31;
    const int w = threadIdx.x >> 5;
    const int strip = blockIdx.x*4 + w;
    if (strip >= NSTRIP) return;      // warps fully independent, no block sync anywhere
    const int ch = blockIdx.z;
    const float* __restrict__ srcp = (sel ? g_bufB : g_bufA) + ch*PLANE;
    float*       __restrict__ dstp = (sel ? g_bufA : g_bufB) + ch*PLANE;
    const float4* __restrict__ src4 = reinterpret_cast<const float4*>(srcp);
    float4*       __restrict__ dst4 = reinterpret_cast<float4*>(dstp);

    const int c4 = strip*28 + t;      // buffer float4 column (max 535 < 544)
    const int r0 = blockIdx.y*SROWS;
    const int rend = min(r0 + SROWS, DOM);   // rend - r0 always even (36 or 10)

    // warm-up: sT = buffer rows r0+1..r0+8, sB = rows r0+8..r0+15, xc = row r0+8
    P4 sT; sT.ab = 0; sT.cd = 0;
    P4 sB; sB.ab = 0; sB.cd = 0;
    P4 xc; xc.ab = 0; xc.cd = 0;
    #pragma unroll
    for (int k = 1; k <= 15; ++k) {
        P4 v = ldp4(&src4[(r0+k)*W4 + c4]);
        if (k <= 8) sT = p4add(sT, v);
        if (k >= 8) sB = p4add(sB, v);
        if (k == 8) xc = v;
    }

    const bool isOut = (t >= 2) && (t < 30) && (c4 <= 517);
    const bool full4 = (c4 <= 516);

    // prefetch first pair's first-touch rows (i+16, i+17); plain __ldg, no hints
    P4 pC = ldp4(&src4[(r0+16)*W4 + c4]);
    P4 pF = ldp4(&src4[(r0+17)*W4 + c4]);

    for (int i = r0; i < rend; i += 2) {
        // re-read rows (L1/L2-resident)
        P4 rA = ldp4(&src4[(i+9)*W4  + c4]);   // aT for row i; center of row i+1
        P4 rB = ldp4(&src4[(i+1)*W4  + c4]);   // bT for row i
        P4 rD = ldp4(&src4[(i+10)*W4 + c4]);   // aT for row i+1; next center
        P4 rE = ldp4(&src4[(i+2)*W4  + c4]);   // bT for row i+1
        P4 rC = pC;                            // aB for row i   (prefetched)
        P4 rF = pF;                            // aB for row i+1 (prefetched)
        // prefetch next pair's first-touch rows (rows <= 2079 < HB, always in-bounds)
        pC = ldp4(&src4[(i+18)*W4 + c4]);
        pF = ldp4(&src4[(i+19)*W4 + c4]);

        // hoist row-(i+1) sums so both epilogues are independent early
        P4 sT1 = p4sub(p4add(sT, rA), rB);
        P4 sB1 = p4sub(p4add(sB, rC), xc);

        do_row<FINAL>(sT, sB, xc, i, dst4, dstp, outp, ch, c4, isOut, full4);
        do_row<FINAL>(sT1, sB1, rA, i+1, dst4, dstp, outp, ch, c4, isOut, full4);

        sT = p4sub(p4add(sT1, rD), rE);
        sB = p4sub(p4add(sB1, rF), rA);
        xc = rD;
    }
}

extern "C" void kernel_launch(void* const* d_in, const int* in_sizes, int n_in,
                              void* d_out, int out_size) {
    (void)in_sizes; (void)n_in; (void)out_size;
    const float* img = (const float*)d_in[0];   // d_in[1], d_in[2] are fixed constant kernels
    float* out = (float*)d_out;

    pad_kernel<<<dim3((DOM + 255)/256, DOM, 3), 256>>>(img);

    // iterations 0..8 ping-pong between buffers (it0: A->B, it8: A->B)
    for (int it = 0; it < NITER-1; ++it)
        iter_kernel_t<false><<<dim3(5, NRB, 3), 128>>>(it & 1, nullptr);

    // final iteration reads bufB, writes the cropped result directly to d_out (HWC)
    iter_kernel_t<true><<<dim3(5, NRB, 3), 128>>>(1, out);
}

// round 14
// speedup vs baseline: 1.0791x; 1.0721x over previous
#include <cuda_runtime.h>

// ---------------- geometry ----------------
#define RAD    7
#define IMG    2048
#define DOM    2062            // IMG + 2*RAD : iterated domain
#define GUARD  8               // zero guard band around DOM (zero-pad semantics)
#define WB     2176            // buffer width in floats
#define W4     (WB/4)
#define HB     2080            // buffer height
#define PLANE  (HB*WB)
#define NSTRIP 19              // 19 strips * 28 float4 = 532 >= 516 domain float4 cols
#define SROWS  30              // even; 5 x 69 x 3 = 1035 blocks <= 148 SM x 7 = 1036 (one wave)
#define NRB    69              // 68*30 = 2040; last block rows 2040..2061 = 22 (even)
#define NITER  10

// ping-pong state, planar per channel, zero-initialized at module load;
// guard bands are NEVER written -> stay zero across all graph replays
__device__ float g_bufA[3*PLANE];
__device__ float g_bufB[3*PLANE];

// ---------------- pad: img (HWC, edge-pad 7) -> bufA domain region only ----------------
__global__ void pad_kernel(const float* __restrict__ img) {
    int bc = GUARD + blockIdx.x*blockDim.x + threadIdx.x;   // domain col in buffer coords
    int br = GUARD + blockIdx.y;                            // domain row in buffer coords
    int ch = blockIdx.z;
    if (bc >= GUARD+DOM) return;
    int u = br - (GUARD+RAD);
    int w = bc - (GUARD+RAD);
    u = min(max(u,0), IMG-1);
    w = min(max(w,0), IMG-1);
    g_bufA[ch*PLANE + br*WB + bc] = img[(u*IMG + w)*3 + ch];
}

// ---------------- packed f32x2 helpers (Blackwell) ----------------
typedef unsigned long long u64;
#define NEG1P 0xBF800000BF800000ULL     // {-1.0f, -1.0f}

__device__ __forceinline__ u64 pk2(float lo, float hi){
    u64 r; asm("mov.b64 %0, {%1, %2};" : "=l"(r) : "f"(lo), "f"(hi)); return r;
}
__device__ __forceinline__ void up2(u64 v, float& lo, float& hi){
    asm("mov.b64 {%0, %1}, %2;" : "=f"(lo), "=f"(hi) : "l"(v));
}
__device__ __forceinline__ u64 fadd2(u64 a, u64 b){
    u64 r; asm("add.rn.f32x2 %0, %1, %2;" : "=l"(r) : "l"(a), "l"(b)); return r;
}
__device__ __forceinline__ u64 fmul2(u64 a, u64 b){
    u64 r; asm("mul.rn.f32x2 %0, %1, %2;" : "=l"(r) : "l"(a), "l"(b)); return r;
}
__device__ __forceinline__ u64 ffma2(u64 a, u64 b, u64 c){
    u64 r; asm("fma.rn.f32x2 %0, %1, %2, %3;" : "=l"(r) : "l"(a), "l"(b), "l"(c)); return r;
}
__device__ __forceinline__ u64 fsub2(u64 a, u64 b){     // a - b (exact: fma(b,-1,a))
    return ffma2(b, NEG1P, a);
}

struct P4 { u64 ab, cd; };               // packed float4: {x,y},{z,w}
__device__ __forceinline__ P4 p4add(P4 a, P4 b){ P4 r; r.ab=fadd2(a.ab,b.ab); r.cd=fadd2(a.cd,b.cd); return r; }
__device__ __forceinline__ P4 p4sub(P4 a, P4 b){ P4 r; r.ab=fsub2(a.ab,b.ab); r.cd=fsub2(a.cd,b.cd); return r; }
__device__ __forceinline__ P4 ldp4(const float4* p){
    float4 v = __ldg(p);
    P4 r; r.ab = pk2(v.x, v.y); r.cd = pk2(v.z, v.w); return r;
}

// rotate-left-1 key: (abs_bits << 1) | sign  — unsigned order == |value| order,
// bijective with the float bits (recover via rotate-right-1)
__device__ __forceinline__ unsigned keyof(float d) {
    unsigned b = __float_as_uint(d);
    return __funnelshift_l(b, b, 1);
}

// 8-wide left/right window sums for this lane's 4 columns, all-shuffle exchange.
// Lane t owns chunk cols [4t, 4t+4). With w[k] = value at col 4(t-2)+k:
//   l[j] = sum w[j+1 .. j+8], r[j] = sum w[j+8 .. j+15]
__device__ __forceinline__ void awin(float ax, float ay, float az, float aw,
                                     float* l, float* r) {
    const unsigned FULL = 0xffffffffu;
    float P2 = ax + ay;
    float P3 = P2 + az;
    float S2 = az + aw;
    float S3 = ay + S2;
    float C  = P3 + aw;
    float uS1 = __shfl_up_sync  (FULL, aw, 2);
    float uS2 = __shfl_up_sync  (FULL, S2, 2);
    float uS3 = __shfl_up_sync  (FULL, S3, 2);
    float uC  = __shfl_up_sync  (FULL, C,  1);
    float dC  = __shfl_down_sync(FULL, C,  1);
    float dP1 = __shfl_down_sync(FULL, ax, 2);
    float dP2 = __shfl_down_sync(FULL, P2, 2);
    float dP3 = __shfl_down_sync(FULL, P3, 2);
    l[0] = uS3 + uC + ax;
    l[1] = uS2 + uC + P2;
    l[2] = uS1 + uC + P3;
    l[3] = uC  + C;
    r[0] = C   + dC;
    r[1] = S3  + dC + dP1;
    r[2] = S2  + dC + dP2;
    r[3] = aw  + dC + dP3;
}

// full side-window pass for one row; unconditional compute, predicated store.
// FINAL=false: store float4 into dst buffer.  FINAL=true: scatter HWC into outp.
template<bool FINAL>
__device__ __forceinline__ void do_row(P4 sT, P4 sB, P4 xc, int i,
                                       float4* __restrict__ dst4,
                                       float*  __restrict__ dstp,
                                       float*  __restrict__ outp, int ch,
                                       int c4, bool isOut, bool full4) {
    const u64 S8p  = pk2(1.0f/64.0f,  1.0f/64.0f);
    const u64 S15p = pk2(1.0f/120.0f, 1.0f/120.0f);

    // full 15-row vertical sum (packed)
    u64 sVab = fsub2(fadd2(sT.ab, sB.ab), xc.ab);
    u64 sVcd = fsub2(fadd2(sT.cd, sB.cd), xc.cd);

    float t0,t1,t2,t3, b0,b1,b2,b3, v0,v1,v2,v3;
    up2(sT.ab, t0,t1); up2(sT.cd, t2,t3);
    up2(sB.ab, b0,b1); up2(sB.cd, b2,b3);
    up2(sVab,  v0,v1); up2(sVcd,  v2,v3);

    float lT[4], rT[4], lB[4], rB[4], lV[4], rV[4];
    awin(t0,t1,t2,t3, lT, rT);
    awin(b0,b1,b2,b3, lB, rB);
    awin(v0,v1,v2,v3, lV, rV);

    float res[4];
    #pragma unroll
    for (int p = 0; p < 2; ++p) {       // pixel pairs (j0,j1) and (j2,j3)
        u64 xp  = p ? xc.cd : xc.ab;
        u64 fTp = p ? sT.cd : sT.ab;
        u64 fBp = p ? sB.cd : sB.ab;
        u64 lTp = pk2(lT[2*p], lT[2*p+1]);
        u64 rTp = pk2(rT[2*p], rT[2*p+1]);
        u64 lBp = pk2(lB[2*p], lB[2*p+1]);
        u64 rBp = pk2(rB[2*p], rB[2*p+1]);
        u64 lVp = pk2(lV[2*p], lV[2*p+1]);
        u64 rVp = pk2(rV[2*p], rV[2*p+1]);

        u64 nx  = fmul2(xp, NEG1P);                 // exact -x pair
        u64 fAp = fsub2(fadd2(lTp, rTp), fTp);      // full-15 horiz of top sums (N)
        u64 fSp = fsub2(fadd2(lBp, rBp), fBp);      // full-15 horiz of bottom sums (S)

        // channel order matches reference stack: NW NE SW SE N S W E
        u64 d0 = ffma2(lTp, S8p,  nx);
        u64 d1 = ffma2(rTp, S8p,  nx);
        u64 d2 = ffma2(lBp, S8p,  nx);
        u64 d3 = ffma2(rBp, S8p,  nx);
        u64 d4 = ffma2(fAp, S15p, nx);
        u64 d5 = ffma2(fSp, S15p, nx);
        u64 d6 = ffma2(lVp, S15p, nx);
        u64 d7 = ffma2(rVp, S15p, nx);

        float e0,f0_, e1,f1_, e2,f2_, e3,f3_, e4,f4_, e5,f5_, e6,f6_, e7,f7_;
        up2(d0, e0,f0_); up2(d1, e1,f1_); up2(d2, e2,f2_); up2(d3, e3,f3_);
        up2(d4, e4,f4_); up2(d5, e5,f5_); up2(d6, e6,f6_); up2(d7, e7,f7_);
        float xlo, xhi; up2(xp, xlo, xhi);

        {   // element 2p : min-|d| via rotated-bits unsigned keys, depth-3 IMNMX tree
            unsigned m = min(min(min(keyof(e0),keyof(e1)), min(keyof(e2),keyof(e3))),
                             min(min(keyof(e4),keyof(e5)), min(keyof(e6),keyof(e7))));
            res[2*p] = xlo + __uint_as_float(__funnelshift_r(m, m, 1));
        }
        {   // element 2p+1
            unsigned m = min(min(min(keyof(f0_),keyof(f1_)), min(keyof(f2_),keyof(f3_))),
                             min(min(keyof(f4_),keyof(f5_)), min(keyof(f6_),keyof(f7_))));
            res[2*p+1] = xhi + __uint_as_float(__funnelshift_r(m, m, 1));
        }
    }

    if (FINAL) {
        // write crop region directly to d_out (HWC); no buffer write needed
        int y = i - RAD;
        if (isOut && (unsigned)y < (unsigned)IMG) {
            #pragma unroll
            for (int j = 0; j < 4; ++j) {
                int x = 4*c4 + j - (GUARD+RAD);
                if ((unsigned)x < (unsigned)IMG)
                    outp[((size_t)y*IMG + x)*3 + ch] = res[j];
            }
        }
    } else {
        if (isOut & full4) {
            dst4[(i+8)*W4 + c4] = make_float4(res[0], res[1], res[2], res[3]);
        } else if (isOut) {
            // c4 == 517: only buffer cols 2068, 2069 are inside the domain
            dstp[(i+8)*WB + 4*c4 + 0] = res[0];
            dstp[(i+8)*WB + 4*c4 + 1] = res[1];
        }
    }
}

// ---------------- one full side-window iteration, 2 rows per loop ----------------
template<bool FINAL>
__global__ __launch_bounds__(128,7) void iter_kernel_t(int sel, float* __restrict__ outp) {
    const int t = threadIdx.x & 31;
    const int w = threadIdx.x >> 5;
    const int strip = blockIdx.x*4 + w;
    if (strip >= NSTRIP) return;      // warps fully independent, no block sync anywhere
    const int ch = blockIdx.z;
    const float* __restrict__ srcp = (sel ? g_bufB : g_bufA) + ch*PLANE;
    float*       __restrict__ dstp = (sel ? g_bufA : g_bufB) + ch*PLANE;
    const float4* __restrict__ src4 = reinterpret_cast<const float4*>(srcp);
    float4*       __restrict__ dst4 = reinterpret_cast<float4*>(dstp);

    const int c4 = strip*28 + t;      // buffer float4 column (max 535 < 544)
    const int r0 = blockIdx.y*SROWS;
    const int rend = min(r0 + SROWS, DOM);   // rend - r0 always even (30 or 22)

    // warm-up: sT = buffer rows r0+1..r0+8, sB = rows r0+8..r0+15, xc = row r0+8
    P4 sT; sT.ab = 0; sT.cd = 0;
    P4 sB; sB.ab = 0; sB.cd = 0;
    P4 xc; xc.ab = 0; xc.cd = 0;
    #pragma unroll
    for (int k = 1; k <= 15; ++k) {
        P4 v = ldp4(&src4[(r0+k)*W4 + c4]);
        if (k <= 8) sT = p4add(sT, v);
        if (k >= 8) sB = p4add(sB, v);
        if (k == 8) xc = v;
    }

    const bool isOut = (t >= 2) && (t < 30) && (c4 <= 517);
    const bool full4 = (c4 <= 516);

    for (int i = r0; i < rend; i += 2) {
        // all six slide inputs for the row pair, issued up front
        P4 rA = ldp4(&src4[(i+9)*W4  + c4]);   // aT for row i; center of row i+1
        P4 rB = ldp4(&src4[(i+1)*W4  + c4]);   // bT for row i
        P4 rC = ldp4(&src4[(i+16)*W4 + c4]);   // aB for row i
        P4 rD = ldp4(&src4[(i+10)*W4 + c4]);   // aT for row i+1; next center
        P4 rE = ldp4(&src4[(i+2)*W4  + c4]);   // bT for row i+1
        P4 rF = ldp4(&src4[(i+17)*W4 + c4]);   // aB for row i+1

        // hoist row-(i+1) sums so both epilogues are dataflow-independent early
        P4 sT1 = p4sub(p4add(sT, rA), rB);
        P4 sB1 = p4sub(p4add(sB, rC), xc);

        do_row<FINAL>(sT, sB, xc, i, dst4, dstp, outp, ch, c4, isOut, full4);
        do_row<FINAL>(sT1, sB1, rA, i+1, dst4, dstp, outp, ch, c4, isOut, full4);

        sT = p4sub(p4add(sT1, rD), rE);
        sB = p4sub(p4add(sB1, rF), rA);
        xc = rD;
    }
}

extern "C" void kernel_launch(void* const* d_in, const int* in_sizes, int n_in,
                              void* d_out, int out_size) {
    (void)in_sizes; (void)n_in; (void)out_size;
    const float* img = (const float*)d_in[0];   // d_in[1], d_in[2] are fixed constant kernels
    float* out = (float*)d_out;

    pad_kernel<<<dim3((DOM + 255)/256, DOM, 3), 256>>>(img);

    // iterations 0..8 ping-pong between buffers (it0: A->B, it8: A->B)
    for (int it = 0; it < NITER-1; ++it)
        iter_kernel_t<false><<<dim3(5, NRB, 3), 128>>>(it & 1, nullptr);

    // final iteration reads bufB, writes the cropped result directly to d_out (HWC)
    iter_kernel_t<true><<<dim3(5, NRB, 3), 128>>>(1, out);
}